// round 3
// baseline (speedup 1.0000x reference)
#include <cuda_runtime.h>
#include <cstdint>

// Problem constants (from reference):
//   input_ids : [256, 512]   int32
//   item_codes: [1000000, 8] int32
//   centroids : [8, 256, 64] float32
//   output    : [256, 512, 512] float32
// out[b,s,:] = concat_m centroids[m, min(item_codes[input_ids[b,s], m], 255), :]
// zeroed where input_ids == 0.

static constexpr int PQ_M = 8;
static constexpr int SUB_DIM = 64;
static constexpr int EMB = PQ_M * SUB_DIM;        // 512 floats
static constexpr int F4_PER_TOKEN = EMB / 4;      // 128 float4
static constexpr int F4_PER_SUB = SUB_DIM / 4;    // 16 float4 per subvector

__global__ void __launch_bounds__(256)
pq_gather_kernel(const int* __restrict__ input_ids,
                 const int* __restrict__ item_codes,
                 const float4* __restrict__ centroids4,   // [8][256][16] float4
                 float4* __restrict__ out4,               // [tokens][128] float4
                 int n_tokens)
{
    const int warp = (blockIdx.x * blockDim.x + threadIdx.x) >> 5;
    const int lane = threadIdx.x & 31;
    if (warp >= n_tokens) return;

    const int id = input_ids[warp];                 // uniform per warp (broadcast)
    float4* __restrict__ o = out4 + (size_t)warp * F4_PER_TOKEN;

    if (id == 0) {
        // Padding token: write zeros, skip all gathers.
        const float4 z = make_float4(0.f, 0.f, 0.f, 0.f);
        #pragma unroll
        for (int j = 0; j < 4; j++)
            __stcs(o + lane + 32 * j, z);           // streaming store (evict-first)
        return;
    }

    // Lanes 0..7 fetch the 8 PQ codes for this item in one coalesced 32B sector.
    int mycode = 0;
    if (lane < PQ_M) {
        mycode = __ldg(item_codes + (size_t)id * PQ_M + lane);
        mycode = min(mycode, 255);
    }

    // Each lane writes float4 slots {lane, lane+32, lane+64, lane+96} of the
    // 128-float4 embedding. Slot f belongs to sub-dim m = f>>4, element f&15.
    #pragma unroll
    for (int j = 0; j < 4; j++) {
        const int f = lane + 32 * j;
        const int m = f >> 4;                       // 0..7
        const int c = __shfl_sync(0xffffffffu, mycode, m);
        const float4 v = __ldg(centroids4 + ((size_t)(m * 256 + c) * F4_PER_SUB) + (f & 15));
        __stcs(o + f, v);                           // protect centroid table in L2
    }
}

extern "C" void kernel_launch(void* const* d_in, const int* in_sizes, int n_in,
                              void* d_out, int out_size)
{
    const int*    input_ids  = (const int*)d_in[0];     // [B*S]
    const int*    item_codes = (const int*)d_in[1];     // [NUM_ITEMS*8]
    const float4* centroids4 = (const float4*)d_in[2];  // [8*256*16] float4
    float4*       out4       = (float4*)d_out;

    const int n_tokens = in_sizes[0];                   // 131072
    const int warps_per_block = 256 / 32;               // 8
    const int blocks = (n_tokens + warps_per_block - 1) / warps_per_block;

    pq_gather_kernel<<<blocks, 256>>>(input_ids, item_codes, centroids4, out4, n_tokens);
}